// round 2
// baseline (speedup 1.0000x reference)
#include <cuda_runtime.h>
#include <cuda_bf16.h>

#define N0 65536
#define N1 16384
#define N2 4096
#define N3 1024
#define N4 256
#define C  256

// output offsets (floats): pe4, pe3, pe2, pe1, pe0
#define OFF4 0
#define OFF3 (N4*C)                       // 65536
#define OFF2 (OFF3 + N3*C)                // 327680
#define OFF1 (OFF2 + N2*C)                // 1376256
#define OFF0 (OFF1 + N1*C)                // 5570560

// -------- scratch (device globals; no allocation allowed) --------
__device__ float g_f0[(size_t)N0 * C];    // 64 MB
__device__ float g_cls4[C];
__device__ float g_xyz1[N1 * 3];
__device__ float g_xyz2[N2 * 3];
__device__ float g_xyz3[N3 * 3];
__device__ float g_xyz4[N4 * 3];
__device__ int   g_k34[N3];
__device__ int   g_k23[N2];
__device__ int   g_k12[N1];

// -------- gather xyz rows --------
__global__ void gather_kernel(const float* __restrict__ xyz0,
                              const int* __restrict__ idx,
                              float* __restrict__ out, int M) {
    int i = blockIdx.x * blockDim.x + threadIdx.x;
    if (i < M) {
        int s = idx[i];
        out[i * 3 + 0] = xyz0[s * 3 + 0];
        out[i * 3 + 1] = xyz0[s * 3 + 1];
        out[i * 3 + 2] = xyz0[s * 3 + 2];
    }
}

// -------- f0 = xyz0 @ W_all + b_all --------
__global__ void f0_kernel(const float* __restrict__ xyz0,
                          const float* __restrict__ W,
                          const float* __restrict__ b,
                          float* __restrict__ f0) {
    int row = blockIdx.x;
    int t = threadIdx.x;
    float x = xyz0[row * 3 + 0];
    float y = xyz0[row * 3 + 1];
    float z = xyz0[row * 3 + 2];
    f0[(size_t)row * C + t] =
        fmaf(x, W[t], fmaf(y, W[C + t], fmaf(z, W[2 * C + t], b[t])));
}

// -------- cls4 = max over first 256 rows of f0 (per column) --------
__global__ void cls4_kernel(const float* __restrict__ f0, float* __restrict__ cls4) {
    int t = threadIdx.x;
    float m = -3.4e38f;
    for (int i = 0; i < N4; i++) m = fmaxf(m, f0[(size_t)i * C + t]);
    cls4[t] = m;
}

// -------- 1-NN: for each query row, argmin over refs of squared dist --------
// d = |r|^2 - 2 q.r  (|q|^2 dropped: monotone-equivalent). Strict < keeps first index.
__global__ void nn_kernel(const float* __restrict__ q, int Mq,
                          const float* __restrict__ ref, int Mr,
                          int* __restrict__ out) {
    const int CH = 1024;
    __shared__ float rx[CH], ry[CH], rz[CH], rn[CH];
    int tid = blockIdx.x * blockDim.x + threadIdx.x;
    float qx = q[tid * 3 + 0];
    float qy = q[tid * 3 + 1];
    float qz = q[tid * 3 + 2];
    float m2x = -2.0f * qx, m2y = -2.0f * qy, m2z = -2.0f * qz;
    float best = 3.4e38f;
    int bi = 0;
    for (int base = 0; base < Mr; base += CH) {
        int n = min(CH, Mr - base);
        for (int j = threadIdx.x; j < n; j += blockDim.x) {
            float x = ref[(base + j) * 3 + 0];
            float y = ref[(base + j) * 3 + 1];
            float z = ref[(base + j) * 3 + 2];
            rx[j] = x; ry[j] = y; rz[j] = z;
            rn[j] = x * x + y * y + z * z;
        }
        __syncthreads();
        #pragma unroll 4
        for (int j = 0; j < n; j++) {
            float d = fmaf(m2x, rx[j], fmaf(m2y, ry[j], fmaf(m2z, rz[j], rn[j])));
            if (d < best) { best = d; bi = base + j; }
        }
        __syncthreads();
    }
    out[tid] = bi;
}

// -------- fused level kernel --------
// A[row] = [ f_nei(row) (256) | f0[row] (256) ],  out[row] = A[row] @ P + pb
// f_nei(row) = (level4 ? cls4 : pe_prev[k[row]]) + delta @ W + b
// delta = level4 ? xyzq[row] : xyzq[row] - xyzr[k[row]]
// Block: 256 threads, TM=16 rows/block. Thread t owns output column t.
#define TM 16
__global__ void __launch_bounds__(256)
pe_kernel(const float* __restrict__ pe_prev,
          const int* __restrict__ knn,
          const float* __restrict__ xyzq,
          const float* __restrict__ xyzr,
          const float* __restrict__ f0,
          const float* __restrict__ W,
          const float* __restrict__ b,
          const float* __restrict__ P,
          const float* __restrict__ pb,
          float* __restrict__ out,
          int level4) {
    __shared__ __align__(16) float As[2 * C * TM];  // 32 KB, k-major: As[k*TM + r]
    __shared__ float dxs[TM][3];
    __shared__ int ks[TM];

    const int t = threadIdx.x;
    const int rowbase = blockIdx.x * TM;

    if (t < TM) {
        int row = rowbase + t;
        float qx = xyzq[row * 3 + 0];
        float qy = xyzq[row * 3 + 1];
        float qz = xyzq[row * 3 + 2];
        if (level4) {
            ks[t] = 0;
            dxs[t][0] = qx; dxs[t][1] = qy; dxs[t][2] = qz;
        } else {
            int kk = knn[row];
            ks[t] = kk;
            dxs[t][0] = qx - xyzr[kk * 3 + 0];
            dxs[t][1] = qy - xyzr[kk * 3 + 1];
            dxs[t][2] = qz - xyzr[kk * 3 + 2];
        }
    }
    __syncthreads();

    // Stage A tile, k-major. Thread t handles row r = t&15, k-group = t>>4.
    // STS address word = k*16 + r -> lane-id-linear within warp -> conflict-free.
    {
        const int r = t & (TM - 1);
        const int row = rowbase + r;
        const float dx = dxs[r][0], dy = dxs[r][1], dz = dxs[r][2];
        const int krow = ks[r];
        const float* prow = level4 ? pe_prev : (pe_prev + (size_t)krow * C);
        const float* frow = f0 + (size_t)row * C;
        #pragma unroll
        for (int it = 0; it < 16; it++) {
            int k = (t >> 4) + 16 * it;
            float nei = __ldg(prow + k);
            float v = nei + fmaf(dx, __ldg(W + k),
                          fmaf(dy, __ldg(W + C + k),
                          fmaf(dz, __ldg(W + 2 * C + k), __ldg(b + k))));
            As[k * TM + (t & (TM - 1))] = v;
            As[(C + k) * TM + (t & (TM - 1))] = __ldg(frow + k);
        }
    }
    __syncthreads();

    // GEMM: thread t computes column t for 16 rows, packed as 8 f32x2 accumulators.
    unsigned long long acc[TM / 2];
    #pragma unroll
    for (int j = 0; j < TM / 2; j++) acc[j] = 0ULL;

    const float* Pc = P + t;
    #pragma unroll 4
    for (int k = 0; k < 2 * C; k++) {
        float pv = __ldg(Pc + (size_t)k * C);
        unsigned long long pv2;
        asm("mov.b64 %0, {%1, %2};" : "=l"(pv2) : "f"(pv), "f"(pv));
        const unsigned long long* a2 =
            reinterpret_cast<const unsigned long long*>(&As[k * TM]);
        #pragma unroll
        for (int j = 0; j < TM / 2; j++) {
            asm("fma.rn.f32x2 %0, %1, %2, %0;"
                : "+l"(acc[j]) : "l"(a2[j]), "l"(pv2));
        }
    }

    float pbv = pb[t];
    #pragma unroll
    for (int j = 0; j < TM / 2; j++) {
        float lo, hi;
        asm("mov.b64 {%0, %1}, %2;" : "=f"(lo), "=f"(hi) : "l"(acc[j]));
        out[(size_t)(rowbase + 2 * j) * C + t]     = lo + pbv;
        out[(size_t)(rowbase + 2 * j + 1) * C + t] = hi + pbv;
    }
}

extern "C" void kernel_launch(void* const* d_in, const int* in_sizes, int n_in,
                              void* d_out, int out_size) {
    const float* xyz0 = (const float*)d_in[0];
    const int* idx0 = (const int*)d_in[1];
    const int* idx1 = (const int*)d_in[2];
    const int* idx2 = (const int*)d_in[3];
    const int* idx3 = (const int*)d_in[4];
    const int* idx4 = (const int*)d_in[5];
    const float* W_all = (const float*)d_in[6];
    const float* b_all = (const float*)d_in[7];
    const float* W4 = (const float*)d_in[8];
    const float* b4 = (const float*)d_in[9];
    const float* W3 = (const float*)d_in[10];
    const float* b3 = (const float*)d_in[11];
    const float* W2 = (const float*)d_in[12];
    const float* b2 = (const float*)d_in[13];
    const float* W1 = (const float*)d_in[14];
    const float* b1 = (const float*)d_in[15];
    const float* W0 = (const float*)d_in[16];
    const float* b0 = (const float*)d_in[17];
    const float* P4 = (const float*)d_in[18];
    const float* pb4 = (const float*)d_in[19];
    const float* P3 = (const float*)d_in[20];
    const float* pb3 = (const float*)d_in[21];
    const float* P2 = (const float*)d_in[22];
    const float* pb2 = (const float*)d_in[23];
    const float* P1 = (const float*)d_in[24];
    const float* pb1 = (const float*)d_in[25];
    const float* P0 = (const float*)d_in[26];
    const float* pb0 = (const float*)d_in[27];
    float* out = (float*)d_out;

    float *f0p, *cls4p, *x1, *x2, *x3, *x4;
    int *k34, *k23, *k12;
    cudaGetSymbolAddress((void**)&f0p, g_f0);
    cudaGetSymbolAddress((void**)&cls4p, g_cls4);
    cudaGetSymbolAddress((void**)&x1, g_xyz1);
    cudaGetSymbolAddress((void**)&x2, g_xyz2);
    cudaGetSymbolAddress((void**)&x3, g_xyz3);
    cudaGetSymbolAddress((void**)&x4, g_xyz4);
    cudaGetSymbolAddress((void**)&k34, g_k34);
    cudaGetSymbolAddress((void**)&k23, g_k23);
    cudaGetSymbolAddress((void**)&k12, g_k12);

    // gathers
    gather_kernel<<<(N1 + 255) / 256, 256>>>(xyz0, idx1, x1, N1);
    gather_kernel<<<(N2 + 255) / 256, 256>>>(xyz0, idx2, x2, N2);
    gather_kernel<<<(N3 + 255) / 256, 256>>>(xyz0, idx3, x3, N3);
    gather_kernel<<<(N4 + 255) / 256, 256>>>(xyz0, idx4, x4, N4);

    // f0 and cls4
    f0_kernel<<<N0, 256>>>(xyz0, W_all, b_all, f0p);
    cls4_kernel<<<1, 256>>>(f0p, cls4p);

    // nearest-neighbor maps (depend only on gathers)
    nn_kernel<<<N3 / 256, 256>>>(x3, N3, x4, N4, k34);
    nn_kernel<<<N2 / 256, 256>>>(x2, N2, x3, N3, k23);
    nn_kernel<<<N1 / 256, 256>>>(x1, N1, x2, N2, k12);

    // level chain (pe4 -> pe0), written directly to d_out
    pe_kernel<<<N4 / TM, 256>>>(cls4p, k34, x4, x4, f0p, W4, b4, P4, pb4, out + OFF4, 1);
    pe_kernel<<<N3 / TM, 256>>>(out + OFF4, k34, x3, x4, f0p, W3, b3, P3, pb3, out + OFF3, 0);
    pe_kernel<<<N2 / TM, 256>>>(out + OFF3, k23, x2, x3, f0p, W2, b2, P2, pb2, out + OFF2, 0);
    pe_kernel<<<N1 / TM, 256>>>(out + OFF2, k12, x1, x2, f0p, W1, b1, P1, pb1, out + OFF1, 0);
    pe_kernel<<<N0 / TM, 256>>>(out + OFF1, idx0, xyz0, x1, f0p, W0, b0, P0, pb0, out + OFF0, 0);
}

// round 4
// speedup vs baseline: 1.5549x; 1.5549x over previous
#include <cuda_runtime.h>
#include <cstdint>

#define NL0 65536
#define NL1 16384
#define NL2 4096
#define NL3 1024
#define NL4 256
#define C   256
#define K2  512

#define OFF4 0
#define OFF3 (NL4*C)
#define OFF2 (OFF3 + NL3*C)
#define OFF1 (OFF2 + NL2*C)
#define OFF0 (OFF1 + NL1*C)

__device__ float g_f0[(size_t)NL0 * C];
__device__ float g_Bh[5][K2 * C];     // P hi, fragment-major
__device__ float g_Bl[5][K2 * C];     // P lo residual, fragment-major
__device__ float g_cls4[C];
__device__ float g_xyz1[NL1 * 3];
__device__ float g_xyz2[NL2 * 3];
__device__ float g_xyz3[NL3 * 3];
__device__ float g_xyz4[NL4 * 3];
__device__ int   g_k34[NL3];
__device__ int   g_k23[NL2];
__device__ int   g_k12[NL1];

__device__ __forceinline__ uint32_t smem_u32(const void* p) {
    uint32_t a;
    asm("{ .reg .u64 t; cvta.to.shared.u64 t, %1; cvt.u32.u64 %0, t; }" : "=r"(a) : "l"(p));
    return a;
}
__device__ __forceinline__ void split2(float v, uint32_t& h, uint32_t& l) {
    asm("cvt.rna.tf32.f32 %0, %1;" : "=r"(h) : "f"(v));
    float r = v - __uint_as_float(h);
    asm("cvt.rna.tf32.f32 %0, %1;" : "=r"(l) : "f"(r));
}
__device__ __forceinline__ void mma8(float* d, const uint32_t* a, const uint32_t* b) {
    asm volatile("mma.sync.aligned.m16n8k8.row.col.f32.tf32.tf32.f32 "
        "{%0,%1,%2,%3}, {%4,%5,%6,%7}, {%8,%9}, {%0,%1,%2,%3};"
        : "+f"(d[0]), "+f"(d[1]), "+f"(d[2]), "+f"(d[3])
        : "r"(a[0]), "r"(a[1]), "r"(a[2]), "r"(a[3]), "r"(b[0]), "r"(b[1]));
}

// ---------- small kernels ----------
__global__ void gather_kernel(const float* __restrict__ xyz0, const int* __restrict__ idx,
                              float* __restrict__ out, int M) {
    int i = blockIdx.x * blockDim.x + threadIdx.x;
    if (i < M) {
        int s = idx[i];
        out[i*3+0] = xyz0[s*3+0]; out[i*3+1] = xyz0[s*3+1]; out[i*3+2] = xyz0[s*3+2];
    }
}
// fragment-major pre-split of P (K2 x C, row-major k*256+n)
// i = ((((chunk*4+ks)*32+nt)*32)+T)*2+reg ; k=chunk*32+ks*8+(T&3)+reg*4 ; n=nt*8+(T>>2)
__global__ void prep_B(const float* __restrict__ P, float* __restrict__ Bh, float* __restrict__ Bl) {
    int i = blockIdx.x * 256 + threadIdx.x;
    int reg = i & 1, T = (i >> 1) & 31, nt = (i >> 6) & 31, ks = (i >> 11) & 3, ch = i >> 13;
    int k = ch*32 + ks*8 + (T & 3) + reg*4;
    int n = nt*8 + (T >> 2);
    uint32_t h, l; split2(P[k*C + n], h, l);
    Bh[i] = __uint_as_float(h);
    Bl[i] = __uint_as_float(l);
}
__global__ void f0_kernel(const float* __restrict__ xyz0, const float* __restrict__ W,
                          const float* __restrict__ b, float* __restrict__ f0) {
    int t = threadIdx.x, rb = blockIdx.x * 8;
    float w0 = W[t], w1 = W[C+t], w2 = W[2*C+t], bb = b[t];
    #pragma unroll
    for (int i = 0; i < 8; i++) {
        int row = rb + i;
        float x = xyz0[row*3+0], y = xyz0[row*3+1], z = xyz0[row*3+2];
        f0[(size_t)row*C + t] = fmaf(x, w0, fmaf(y, w1, fmaf(z, w2, bb)));
    }
}
__global__ void cls4_kernel(const float* __restrict__ f0, float* __restrict__ cls4) {
    int t = threadIdx.x;
    float m = -3.4e38f;
    for (int i = 0; i < NL4; i++) m = fmaxf(m, f0[(size_t)i*C + t]);
    cls4[t] = m;
}
__global__ void nn_kernel(const float* __restrict__ q, const float* __restrict__ ref, int Mr,
                          int* __restrict__ out) {
    const int CH = 1024;
    __shared__ float rx[CH], ry[CH], rz[CH], rn[CH];
    int tid = blockIdx.x * blockDim.x + threadIdx.x;
    float qx = q[tid*3+0], qy = q[tid*3+1], qz = q[tid*3+2];
    float m2x = -2.f*qx, m2y = -2.f*qy, m2z = -2.f*qz;
    float best = 3.4e38f; int bi = 0;
    for (int base = 0; base < Mr; base += CH) {
        int n = min(CH, Mr - base);
        for (int j = threadIdx.x; j < n; j += blockDim.x) {
            float x = ref[(base+j)*3+0], y = ref[(base+j)*3+1], z = ref[(base+j)*3+2];
            rx[j]=x; ry[j]=y; rz[j]=z; rn[j] = x*x + y*y + z*z;
        }
        __syncthreads();
        #pragma unroll 8
        for (int j = 0; j < n; j++) {
            float d = fmaf(m2x, rx[j], fmaf(m2y, ry[j], fmaf(m2z, rz[j], rn[j])));
            if (d < best) { best = d; bi = base + j; }
        }
        __syncthreads();
    }
    out[tid] = bi;
}

// ---------- fused level GEMM: CTA tile M=128, N=128 (grid.y selects N-half) ----------
// smem word offsets within one buffer
#define AH_OFF 0
#define AL_OFF 4352            // 32k * 136 stride
#define BH_OFF 8704
#define BL_OFF 12800           // 4096 words each
#define BUFW   16896           // words per buffer
#define SMEMB  (2 * BUFW * 4)  // 135168 bytes

__global__ void __launch_bounds__(256, 1)
pe_mma(const float* __restrict__ pe_prev, const int* __restrict__ knn,
       const float* __restrict__ xyzq, const float* __restrict__ xyzr,
       const float* __restrict__ f0, const float* __restrict__ W,
       const float* __restrict__ b, const float* __restrict__ Bh,
       const float* __restrict__ Bl, const float* __restrict__ pb,
       float* __restrict__ out, int level4)
{
    extern __shared__ float sm[];
    const int t = threadIdx.x, lane = t & 31, wid = t >> 5;
    const int wm = wid & 3, wn = wid >> 2;
    const int rowbase = blockIdx.x * 128;
    const int yb = blockIdx.y;                 // N-half: cols yb*128..

    // per-thread A row (2 threads/row, 16 k each)
    const int arow = t >> 1, ah = t & 1;
    const int rowg = rowbase + arow;
    float dx, dy, dz;
    const float* prow;
    {
        float qx = xyzq[rowg*3+0], qy = xyzq[rowg*3+1], qz = xyzq[rowg*3+2];
        if (level4) { prow = pe_prev; dx = qx; dy = qy; dz = qz; }
        else {
            int kk = knn[rowg];
            prow = pe_prev + (size_t)kk * C;
            dx = qx - xyzr[kk*3+0]; dy = qy - xyzr[kk*3+1]; dz = qz - xyzr[kk*3+2];
        }
    }

    // ---- B copy (cp.async, fragment-major, straight memcpy of this CTA's N-half) ----
    #define COPY_B(c) do {                                                              \
        const int bw_ = ((c) & 1) * BUFW;                                               \
        const float* sh_ = Bh + (size_t)(c)*8192 + yb*1024 + t*4;                       \
        const float* sl_ = Bl + (size_t)(c)*8192 + yb*1024 + t*4;                       \
        _Pragma("unroll")                                                               \
        for (int ks = 0; ks < 4; ks++) {                                                \
            uint32_t dh_ = smem_u32(&sm[bw_ + BH_OFF + ks*1024 + t*4]);                 \
            uint32_t dl_ = smem_u32(&sm[bw_ + BL_OFF + ks*1024 + t*4]);                 \
            asm volatile("cp.async.cg.shared.global [%0], [%1], 16;"                    \
                :: "r"(dh_), "l"(sh_ + ks*2048) : "memory");                            \
            asm volatile("cp.async.cg.shared.global [%0], [%1], 16;"                    \
                :: "r"(dl_), "l"(sl_ + ks*2048) : "memory");                            \
        }                                                                               \
        asm volatile("cp.async.commit_group;" ::: "memory");                            \
    } while (0)

    // ---- A fill: compute 16 values for (arow, k-half ah), split, store stride-136 ----
    #define FILL_A(c) do {                                                              \
        const int bw_ = ((c) & 1) * BUFW;                                               \
        float v_[16];                                                                   \
        if ((c) < 8) {                                                                  \
            int kg_ = (c)*32 + ah*16;                                                   \
            _Pragma("unroll")                                                           \
            for (int i = 0; i < 4; i++) {                                               \
                float4 ne = *(const float4*)(prow + kg_ + i*4);                         \
                float4 w0 = *(const float4*)(W + kg_ + i*4);                            \
                float4 w1 = *(const float4*)(W + C + kg_ + i*4);                        \
                float4 w2 = *(const float4*)(W + 2*C + kg_ + i*4);                      \
                float4 bb = *(const float4*)(b + kg_ + i*4);                            \
                v_[i*4+0] = ne.x + fmaf(dx,w0.x, fmaf(dy,w1.x, fmaf(dz,w2.x, bb.x)));   \
                v_[i*4+1] = ne.y + fmaf(dx,w0.y, fmaf(dy,w1.y, fmaf(dz,w2.y, bb.y)));   \
                v_[i*4+2] = ne.z + fmaf(dx,w0.z, fmaf(dy,w1.z, fmaf(dz,w2.z, bb.z)));   \
                v_[i*4+3] = ne.w + fmaf(dx,w0.w, fmaf(dy,w1.w, fmaf(dz,w2.w, bb.w)));   \
            }                                                                           \
        } else {                                                                        \
            int kf_ = ((c)-8)*32 + ah*16;                                               \
            const float* fr_ = f0 + (size_t)rowg*C + kf_;                               \
            _Pragma("unroll")                                                           \
            for (int i = 0; i < 4; i++) {                                               \
                float4 q_ = *(const float4*)(fr_ + i*4);                                \
                v_[i*4+0] = q_.x; v_[i*4+1] = q_.y; v_[i*4+2] = q_.z; v_[i*4+3] = q_.w; \
            }                                                                           \
        }                                                                               \
        _Pragma("unroll")                                                               \
        for (int i = 0; i < 16; i++) {                                                  \
            uint32_t h_, l_; split2(v_[i], h_, l_);                                     \
            int k_ = ah*16 + i;                                                         \
            sm[bw_ + AH_OFF + k_*136 + arow] = __uint_as_float(h_);                     \
            sm[bw_ + AL_OFF + k_*136 + arow] = __uint_as_float(l_);                     \
        }                                                                               \
    } while (0)

    // accumulators: 2 m-tiles x 8 n-tiles x 4
    float d[2][8][4];
    #pragma unroll
    for (int i = 0; i < 2; i++)
        #pragma unroll
        for (int j = 0; j < 8; j++)
            #pragma unroll
            for (int q = 0; q < 4; q++) d[i][j][q] = 0.0f;

    COPY_B(0);
    FILL_A(0);
    asm volatile("cp.async.wait_group 0;" ::: "memory");
    __syncthreads();

    const int r0 = lane >> 2, c0 = lane & 3;

    for (int c = 0; c < 16; c++) {
        if (c < 15) { COPY_B(c + 1); FILL_A(c + 1); }

        const int bw = (c & 1) * BUFW;
        #pragma unroll
        for (int ks = 0; ks < 4; ks++) {
            uint32_t Afh[2][4], Afl[2][4];
            #pragma unroll
            for (int tmi = 0; tmi < 2; tmi++) {
                int rb = (wm*2 + tmi)*16 + r0;
                int kc = ks*8 + c0;
                Afh[tmi][0] = __float_as_uint(sm[bw + AH_OFF + kc*136 + rb]);
                Afh[tmi][1] = __float_as_uint(sm[bw + AH_OFF + kc*136 + rb + 8]);
                Afh[tmi][2] = __float_as_uint(sm[bw + AH_OFF + (kc+4)*136 + rb]);
                Afh[tmi][3] = __float_as_uint(sm[bw + AH_OFF + (kc+4)*136 + rb + 8]);
                Afl[tmi][0] = __float_as_uint(sm[bw + AL_OFF + kc*136 + rb]);
                Afl[tmi][1] = __float_as_uint(sm[bw + AL_OFF + kc*136 + rb + 8]);
                Afl[tmi][2] = __float_as_uint(sm[bw + AL_OFF + (kc+4)*136 + rb]);
                Afl[tmi][3] = __float_as_uint(sm[bw + AL_OFF + (kc+4)*136 + rb + 8]);
            }
            uint32_t Bf[8][2];
            #pragma unroll
            for (int nt = 0; nt < 8; nt++) {
                float2 bv = *(const float2*)&sm[bw + BH_OFF + (ks*16 + wn*8 + nt)*64 + 2*lane];
                Bf[nt][0] = __float_as_uint(bv.x); Bf[nt][1] = __float_as_uint(bv.y);
            }
            #pragma unroll
            for (int tmi = 0; tmi < 2; tmi++)
                #pragma unroll
                for (int nt = 0; nt < 8; nt++) mma8(d[tmi][nt], Afh[tmi], Bf[nt]);
            #pragma unroll
            for (int tmi = 0; tmi < 2; tmi++)
                #pragma unroll
                for (int nt = 0; nt < 8; nt++) mma8(d[tmi][nt], Afl[tmi], Bf[nt]);
            #pragma unroll
            for (int nt = 0; nt < 8; nt++) {
                float2 bv = *(const float2*)&sm[bw + BL_OFF + (ks*16 + wn*8 + nt)*64 + 2*lane];
                Bf[nt][0] = __float_as_uint(bv.x); Bf[nt][1] = __float_as_uint(bv.y);
            }
            #pragma unroll
            for (int tmi = 0; tmi < 2; tmi++)
                #pragma unroll
                for (int nt = 0; nt < 8; nt++) mma8(d[tmi][nt], Afh[tmi], Bf[nt]);
        }

        if (c < 15) asm volatile("cp.async.wait_group 0;" ::: "memory");
        __syncthreads();
    }

    // epilogue: D frag map -> (row = r0[+8], col = c0*2 [,+1])
    #pragma unroll
    for (int tmi = 0; tmi < 2; tmi++)
        #pragma unroll
        for (int nt = 0; nt < 8; nt++) {
            int rg = rowbase + (wm*2 + tmi)*16 + r0;
            int cg = yb*128 + wn*64 + nt*8 + c0*2;
            float p0 = __ldg(pb + cg), p1 = __ldg(pb + cg + 1);
            *(float2*)(out + (size_t)rg*C + cg) =
                make_float2(d[tmi][nt][0] + p0, d[tmi][nt][1] + p1);
            *(float2*)(out + (size_t)(rg+8)*C + cg) =
                make_float2(d[tmi][nt][2] + p0, d[tmi][nt][3] + p1);
        }
}

// ---------- host ----------
extern "C" void kernel_launch(void* const* d_in, const int* in_sizes, int n_in,
                              void* d_out, int out_size) {
    const float* xyz0 = (const float*)d_in[0];
    const int* idx0 = (const int*)d_in[1];
    const int* idx1 = (const int*)d_in[2];
    const int* idx2 = (const int*)d_in[3];
    const int* idx3 = (const int*)d_in[4];
    const int* idx4 = (const int*)d_in[5];
    const float* W_all = (const float*)d_in[6];
    const float* b_all = (const float*)d_in[7];
    const float* W4 = (const float*)d_in[8];  const float* b4 = (const float*)d_in[9];
    const float* W3 = (const float*)d_in[10]; const float* b3 = (const float*)d_in[11];
    const float* W2 = (const float*)d_in[12]; const float* b2 = (const float*)d_in[13];
    const float* W1 = (const float*)d_in[14]; const float* b1 = (const float*)d_in[15];
    const float* W0 = (const float*)d_in[16]; const float* b0 = (const float*)d_in[17];
    const float* P4 = (const float*)d_in[18]; const float* pb4 = (const float*)d_in[19];
    const float* P3 = (const float*)d_in[20]; const float* pb3 = (const float*)d_in[21];
    const float* P2 = (const float*)d_in[22]; const float* pb2 = (const float*)d_in[23];
    const float* P1 = (const float*)d_in[24]; const float* pb1 = (const float*)d_in[25];
    const float* P0 = (const float*)d_in[26]; const float* pb0 = (const float*)d_in[27];
    float* out = (float*)d_out;

    float *f0p, *cls4p, *x1, *x2, *x3, *x4, *bh, *bl;
    int *k34, *k23, *k12;
    cudaGetSymbolAddress((void**)&f0p, g_f0);
    cudaGetSymbolAddress((void**)&cls4p, g_cls4);
    cudaGetSymbolAddress((void**)&x1, g_xyz1);
    cudaGetSymbolAddress((void**)&x2, g_xyz2);
    cudaGetSymbolAddress((void**)&x3, g_xyz3);
    cudaGetSymbolAddress((void**)&x4, g_xyz4);
    cudaGetSymbolAddress((void**)&k34, g_k34);
    cudaGetSymbolAddress((void**)&k23, g_k23);
    cudaGetSymbolAddress((void**)&k12, g_k12);
    cudaGetSymbolAddress((void**)&bh, g_Bh);
    cudaGetSymbolAddress((void**)&bl, g_Bl);

    cudaFuncSetAttribute(pe_mma, cudaFuncAttributeMaxDynamicSharedMemorySize, SMEMB);

    gather_kernel<<<(NL1+255)/256, 256>>>(xyz0, idx1, x1, NL1);
    gather_kernel<<<(NL2+255)/256, 256>>>(xyz0, idx2, x2, NL2);
    gather_kernel<<<(NL3+255)/256, 256>>>(xyz0, idx3, x3, NL3);
    gather_kernel<<<(NL4+255)/256, 256>>>(xyz0, idx4, x4, NL4);

    const float* Ps[5] = {P4, P3, P2, P1, P0};
    for (int i = 0; i < 5; i++)
        prep_B<<<512, 256>>>(Ps[i], bh + (size_t)i*K2*C, bl + (size_t)i*K2*C);

    f0_kernel<<<NL0/8, 256>>>(xyz0, W_all, b_all, f0p);
    cls4_kernel<<<1, 256>>>(f0p, cls4p);

    nn_kernel<<<NL3/256, 256>>>(x3, x4, NL4, k34);
    nn_kernel<<<NL2/256, 256>>>(x2, x3, NL3, k23);
    nn_kernel<<<NL1/256, 256>>>(x1, x2, NL2, k12);

    pe_mma<<<dim3(NL4/128, 2), 256, SMEMB>>>(cls4p, k34, x4, x4, f0p, W4, b4,
        bh + 0*(size_t)K2*C, bl + 0*(size_t)K2*C, pb4, out + OFF4, 1);
    pe_mma<<<dim3(NL3/128, 2), 256, SMEMB>>>(out + OFF4, k34, x3, x4, f0p, W3, b3,
        bh + 1*(size_t)K2*C, bl + 1*(size_t)K2*C, pb3, out + OFF3, 0);
    pe_mma<<<dim3(NL2/128, 2), 256, SMEMB>>>(out + OFF3, k23, x2, x3, f0p, W2, b2,
        bh + 2*(size_t)K2*C, bl + 2*(size_t)K2*C, pb2, out + OFF2, 0);
    pe_mma<<<dim3(NL1/128, 2), 256, SMEMB>>>(out + OFF2, k12, x1, x2, f0p, W1, b1,
        bh + 3*(size_t)K2*C, bl + 3*(size_t)K2*C, pb1, out + OFF1, 0);
    pe_mma<<<dim3(NL0/128, 2), 256, SMEMB>>>(out + OFF1, idx0, xyz0, x1, f0p, W0, b0,
        bh + 4*(size_t)K2*C, bl + 4*(size_t)K2*C, pb0, out + OFF0, 0);
}

// round 5
// speedup vs baseline: 2.2991x; 1.4786x over previous
#include <cuda_runtime.h>
#include <cuda_fp16.h>
#include <cstdint>

#define NL0 65536
#define NL1 16384
#define NL2 4096
#define NL3 1024
#define NL4 256
#define C   256
#define K2  512

#define OFF4 0
#define OFF3 (NL4*C)
#define OFF2 (OFF3 + NL3*C)
#define OFF1 (OFF2 + NL2*C)
#define OFF0 (OFF1 + NL1*C)

// fragment-major pre-split B (fp16x2 words): [ch(16)][s(2)][ntg(32)][T(32)][reg(2)]
__device__ uint32_t g_Bh16[5][65536];
__device__ uint32_t g_Bl16[5][65536];
__device__ float g_cls4[C];
__device__ float g_xyz1[NL1 * 3];
__device__ float g_xyz2[NL2 * 3];
__device__ float g_xyz3[NL3 * 3];
__device__ float g_xyz4[NL4 * 3];
__device__ int   g_k34[NL3];
__device__ int   g_k23[NL2];
__device__ int   g_k12[NL1];

__device__ __forceinline__ uint32_t smem_u32(const void* p) {
    uint32_t a;
    asm("{ .reg .u64 t; cvta.to.shared.u64 t, %1; cvt.u32.u64 %0, t; }" : "=r"(a) : "l"(p));
    return a;
}
// split v into fp16 hi + fp16 lo (residual)
__device__ __forceinline__ void splith(float v, __half& h, __half& l) {
    h = __float2half_rn(v);
    l = __float2half_rn(v - __half2float(h));
}
__device__ __forceinline__ uint32_t packh(__half a, __half b) {
    return (uint32_t)__half_as_ushort(a) | ((uint32_t)__half_as_ushort(b) << 16);
}
__device__ __forceinline__ void mma16(float* d, const uint32_t* a, const uint32_t* b) {
    asm volatile("mma.sync.aligned.m16n8k16.row.col.f32.f16.f16.f32 "
        "{%0,%1,%2,%3}, {%4,%5,%6,%7}, {%8,%9}, {%0,%1,%2,%3};"
        : "+f"(d[0]), "+f"(d[1]), "+f"(d[2]), "+f"(d[3])
        : "r"(a[0]), "r"(a[1]), "r"(a[2]), "r"(a[3]), "r"(b[0]), "r"(b[1]));
}

// ---------- small kernels ----------
__global__ void gather_kernel(const float* __restrict__ xyz0, const int* __restrict__ idx,
                              float* __restrict__ out, int M) {
    int i = blockIdx.x * blockDim.x + threadIdx.x;
    if (i < M) {
        int s = idx[i];
        out[i*3+0] = xyz0[s*3+0]; out[i*3+1] = xyz0[s*3+1]; out[i*3+2] = xyz0[s*3+2];
    }
}
// B pre-split: i -> reg,T,ntg,s,ch ; k = ch*32 + s*16 + (T&3)*2 + reg*8 ; n = ntg*8 + T/4
__global__ void prep_B(const float* __restrict__ P, uint32_t* __restrict__ Bh,
                       uint32_t* __restrict__ Bl) {
    int i = blockIdx.x * 256 + threadIdx.x;
    int reg = i & 1, T = (i >> 1) & 31, ntg = (i >> 6) & 31, s = (i >> 11) & 1, ch = i >> 12;
    int k = ch*32 + s*16 + (T & 3)*2 + reg*8;
    int n = ntg*8 + (T >> 2);
    __half h0, l0, h1, l1;
    splith(P[k*C + n], h0, l0);
    splith(P[(k+1)*C + n], h1, l1);
    Bh[i] = packh(h0, h1);
    Bl[i] = packh(l0, l1);
}
// cls4[t] = max over rows 0..255 of xyz0[i].W_all[:,t] + b_all[t]
__global__ void cls4_kernel(const float* __restrict__ xyz0, const float* __restrict__ W,
                            const float* __restrict__ b, float* __restrict__ cls4) {
    int t = threadIdx.x;
    float w0 = W[t], w1 = W[C+t], w2 = W[2*C+t], bb = b[t];
    float m = -3.4e38f;
    for (int i = 0; i < NL4; i++) {
        float v = fmaf(xyz0[i*3+0], w0, fmaf(xyz0[i*3+1], w1, fmaf(xyz0[i*3+2], w2, bb)));
        m = fmaxf(m, v);
    }
    cls4[t] = m;
}
__global__ void nn_kernel(const float* __restrict__ q, const float* __restrict__ ref, int Mr,
                          int* __restrict__ out) {
    const int CH = 1024;
    __shared__ float rx[CH], ry[CH], rz[CH], rn[CH];
    int tid = blockIdx.x * blockDim.x + threadIdx.x;
    float qx = q[tid*3+0], qy = q[tid*3+1], qz = q[tid*3+2];
    float m2x = -2.f*qx, m2y = -2.f*qy, m2z = -2.f*qz;
    float best = 3.4e38f; int bi = 0;
    for (int base = 0; base < Mr; base += CH) {
        int n = min(CH, Mr - base);
        for (int j = threadIdx.x; j < n; j += blockDim.x) {
            float x = ref[(base+j)*3+0], y = ref[(base+j)*3+1], z = ref[(base+j)*3+2];
            rx[j]=x; ry[j]=y; rz[j]=z; rn[j] = x*x + y*y + z*z;
        }
        __syncthreads();
        #pragma unroll 8
        for (int j = 0; j < n; j++) {
            float d = fmaf(m2x, rx[j], fmaf(m2y, ry[j], fmaf(m2z, rz[j], rn[j])));
            if (d < best) { best = d; bi = base + j; }
        }
        __syncthreads();
    }
    out[tid] = bi;
}

// ---------- fused level GEMM (fp16 3-pass split, m16n8k16) ----------
// smem word (u32) offsets within one buffer
#define AH_OFF 0
#define AL_OFF 2176            // 16 kp * 136
#define BH_OFF 4352
#define BL_OFF 6400            // 2048 words each
#define BUFW   8448
#define SMEMB  (2 * BUFW * 4)  // 67584 bytes

__global__ void __launch_bounds__(256, 2)
pe_mma(const float* __restrict__ pe_prev, const int* __restrict__ knn,
       const float* __restrict__ xyzq, const float* __restrict__ xyzr,
       const float* __restrict__ xyz0, const float* __restrict__ W,
       const float* __restrict__ b, const float* __restrict__ Wall,
       const float* __restrict__ ball, const uint32_t* __restrict__ Bh,
       const uint32_t* __restrict__ Bl, const float* __restrict__ pb,
       float* __restrict__ out, int level4)
{
    extern __shared__ uint32_t sm[];
    const int t = threadIdx.x, lane = t & 31, wid = t >> 5;
    const int wm = wid & 3, wn = wid >> 2;
    const int rowbase = blockIdx.x * 128;
    const int yb = blockIdx.y;

    // A fill assignment: row = t&127, k-half = t>>7
    const int arow = t & 127, ah2 = t >> 7;
    const int rowg = rowbase + arow;
    float dx, dy, dz;
    const float* prow;
    {
        float qx = xyzq[rowg*3+0], qy = xyzq[rowg*3+1], qz = xyzq[rowg*3+2];
        if (level4) { prow = pe_prev; dx = qx; dy = qy; dz = qz; }
        else {
            int kk = knn[rowg];
            prow = pe_prev + (size_t)kk * C;
            dx = qx - xyzr[kk*3+0]; dy = qy - xyzr[kk*3+1]; dz = qz - xyzr[kk*3+2];
        }
    }
    const float rx = xyz0[rowg*3+0], ry = xyz0[rowg*3+1], rz = xyz0[rowg*3+2];

    #define COPY_B(c) do {                                                             \
        const int bw_ = ((c) & 1) * BUFW;                                              \
        const uint32_t* s0_ = Bh + (size_t)(c)*4096 + yb*1024 + t*4;                   \
        const uint32_t* s1_ = Bl + (size_t)(c)*4096 + yb*1024 + t*4;                   \
        _Pragma("unroll")                                                              \
        for (int s_ = 0; s_ < 2; s_++) {                                               \
            asm volatile("cp.async.cg.shared.global [%0], [%1], 16;"                   \
                :: "r"(smem_u32(&sm[bw_ + BH_OFF + s_*1024 + t*4])),                   \
                   "l"(s0_ + s_*2048) : "memory");                                     \
            asm volatile("cp.async.cg.shared.global [%0], [%1], 16;"                   \
                :: "r"(smem_u32(&sm[bw_ + BL_OFF + s_*1024 + t*4])),                   \
                   "l"(s1_ + s_*2048) : "memory");                                     \
        }                                                                              \
        asm volatile("cp.async.commit_group;" ::: "memory");                           \
    } while (0)

    #define FILL_A(c) do {                                                             \
        const int bw_ = ((c) & 1) * BUFW;                                              \
        float v_[16];                                                                  \
        if ((c) < 8) {                                                                 \
            int kg_ = (c)*32 + ah2*16;                                                 \
            _Pragma("unroll")                                                          \
            for (int i = 0; i < 4; i++) {                                              \
                float4 ne = *(const float4*)(prow + kg_ + i*4);                        \
                float4 w0 = *(const float4*)(W + kg_ + i*4);                           \
                float4 w1 = *(const float4*)(W + C + kg_ + i*4);                       \
                float4 w2 = *(const float4*)(W + 2*C + kg_ + i*4);                     \
                float4 bb = *(const float4*)(b + kg_ + i*4);                           \
                v_[i*4+0] = ne.x + fmaf(dx,w0.x, fmaf(dy,w1.x, fmaf(dz,w2.x, bb.x)));  \
                v_[i*4+1] = ne.y + fmaf(dx,w0.y, fmaf(dy,w1.y, fmaf(dz,w2.y, bb.y)));  \
                v_[i*4+2] = ne.z + fmaf(dx,w0.z, fmaf(dy,w1.z, fmaf(dz,w2.z, bb.z)));  \
                v_[i*4+3] = ne.w + fmaf(dx,w0.w, fmaf(dy,w1.w, fmaf(dz,w2.w, bb.w)));  \
            }                                                                          \
        } else {                                                                       \
            int kf_ = ((c)-8)*32 + ah2*16;                                             \
            _Pragma("unroll")                                                          \
            for (int i = 0; i < 4; i++) {                                              \
                float4 w0 = *(const float4*)(Wall + kf_ + i*4);                        \
                float4 w1 = *(const float4*)(Wall + C + kf_ + i*4);                    \
                float4 w2 = *(const float4*)(Wall + 2*C + kf_ + i*4);                  \
                float4 bb = *(const float4*)(ball + kf_ + i*4);                        \
                v_[i*4+0] = fmaf(rx,w0.x, fmaf(ry,w1.x, fmaf(rz,w2.x, bb.x)));         \
                v_[i*4+1] = fmaf(rx,w0.y, fmaf(ry,w1.y, fmaf(rz,w2.y, bb.y)));         \
                v_[i*4+2] = fmaf(rx,w0.z, fmaf(ry,w1.z, fmaf(rz,w2.z, bb.z)));         \
                v_[i*4+3] = fmaf(rx,w0.w, fmaf(ry,w1.w, fmaf(rz,w2.w, bb.w)));         \
            }                                                                          \
        }                                                                              \
        _Pragma("unroll")                                                              \
        for (int j = 0; j < 8; j++) {                                                  \
            __half h0_, l0_, h1_, l1_;                                                 \
            splith(v_[2*j], h0_, l0_); splith(v_[2*j+1], h1_, l1_);                    \
            int kp_ = ah2*8 + j;                                                       \
            sm[bw_ + AH_OFF + kp_*136 + arow] = packh(h0_, h1_);                       \
            sm[bw_ + AL_OFF + kp_*136 + arow] = packh(l0_, l1_);                       \
        }                                                                              \
    } while (0)

    float d[2][8][4];
    #pragma unroll
    for (int i = 0; i < 2; i++)
        #pragma unroll
        for (int j = 0; j < 8; j++)
            #pragma unroll
            for (int q = 0; q < 4; q++) d[i][j][q] = 0.0f;

    COPY_B(0);
    FILL_A(0);
    asm volatile("cp.async.wait_group 0;" ::: "memory");
    __syncthreads();

    const int r0 = lane >> 2, c0 = lane & 3;

    for (int c = 0; c < 16; c++) {
        if (c < 15) { COPY_B(c + 1); FILL_A(c + 1); }

        const int bw = (c & 1) * BUFW;
        #pragma unroll
        for (int s = 0; s < 2; s++) {
            uint32_t Afh[2][4], Afl[2][4];
            #pragma unroll
            for (int tmi = 0; tmi < 2; tmi++) {
                int rb = wm*32 + tmi*16 + r0;
                int kp = s*8 + c0;
                Afh[tmi][0] = sm[bw + AH_OFF + kp*136 + rb];
                Afh[tmi][1] = sm[bw + AH_OFF + kp*136 + rb + 8];
                Afh[tmi][2] = sm[bw + AH_OFF + (kp+4)*136 + rb];
                Afh[tmi][3] = sm[bw + AH_OFF + (kp+4)*136 + rb + 8];
                Afl[tmi][0] = sm[bw + AL_OFF + kp*136 + rb];
                Afl[tmi][1] = sm[bw + AL_OFF + kp*136 + rb + 8];
                Afl[tmi][2] = sm[bw + AL_OFF + (kp+4)*136 + rb];
                Afl[tmi][3] = sm[bw + AL_OFF + (kp+4)*136 + rb + 8];
            }
            uint32_t Bf[8][2];
            #pragma unroll
            for (int nt = 0; nt < 8; nt++) {
                int ntl = wn*8 + nt;
                *(uint2*)Bf[nt] = *(const uint2*)&sm[bw + BH_OFF + (s*16 + ntl)*64 + lane*2];
            }
            #pragma unroll
            for (int tmi = 0; tmi < 2; tmi++)
                #pragma unroll
                for (int nt = 0; nt < 8; nt++) mma16(d[tmi][nt], Afh[tmi], Bf[nt]);
            #pragma unroll
            for (int tmi = 0; tmi < 2; tmi++)
                #pragma unroll
                for (int nt = 0; nt < 8; nt++) mma16(d[tmi][nt], Afl[tmi], Bf[nt]);
            #pragma unroll
            for (int nt = 0; nt < 8; nt++) {
                int ntl = wn*8 + nt;
                *(uint2*)Bf[nt] = *(const uint2*)&sm[bw + BL_OFF + (s*16 + ntl)*64 + lane*2];
            }
            #pragma unroll
            for (int tmi = 0; tmi < 2; tmi++)
                #pragma unroll
                for (int nt = 0; nt < 8; nt++) mma16(d[tmi][nt], Afh[tmi], Bf[nt]);
        }

        if (c < 15) asm volatile("cp.async.wait_group 0;" ::: "memory");
        __syncthreads();
    }

    #pragma unroll
    for (int tmi = 0; tmi < 2; tmi++)
        #pragma unroll
        for (int nt = 0; nt < 8; nt++) {
            int rg = rowbase + wm*32 + tmi*16 + r0;
            int cg = yb*128 + wn*64 + nt*8 + c0*2;
            float p0 = __ldg(pb + cg), p1 = __ldg(pb + cg + 1);
            *(float2*)(out + (size_t)rg*C + cg) =
                make_float2(d[tmi][nt][0] + p0, d[tmi][nt][1] + p1);
            *(float2*)(out + (size_t)(rg+8)*C + cg) =
                make_float2(d[tmi][nt][2] + p0, d[tmi][nt][3] + p1);
        }
}

// ---------- host ----------
extern "C" void kernel_launch(void* const* d_in, const int* in_sizes, int n_in,
                              void* d_out, int out_size) {
    const float* xyz0 = (const float*)d_in[0];
    const int* idx0 = (const int*)d_in[1];
    const int* idx1 = (const int*)d_in[2];
    const int* idx2 = (const int*)d_in[3];
    const int* idx3 = (const int*)d_in[4];
    const int* idx4 = (const int*)d_in[5];
    const float* W_all = (const float*)d_in[6];
    const float* b_all = (const float*)d_in[7];
    const float* W4 = (const float*)d_in[8];  const float* b4 = (const float*)d_in[9];
    const float* W3 = (const float*)d_in[10]; const float* b3 = (const float*)d_in[11];
    const float* W2 = (const float*)d_in[12]; const float* b2 = (const float*)d_in[13];
    const float* W1 = (const float*)d_in[14]; const float* b1 = (const float*)d_in[15];
    const float* W0 = (const float*)d_in[16]; const float* b0 = (const float*)d_in[17];
    const float* P4 = (const float*)d_in[18]; const float* pb4 = (const float*)d_in[19];
    const float* P3 = (const float*)d_in[20]; const float* pb3 = (const float*)d_in[21];
    const float* P2 = (const float*)d_in[22]; const float* pb2 = (const float*)d_in[23];
    const float* P1 = (const float*)d_in[24]; const float* pb1 = (const float*)d_in[25];
    const float* P0 = (const float*)d_in[26]; const float* pb0 = (const float*)d_in[27];
    float* out = (float*)d_out;

    float *cls4p, *x1, *x2, *x3, *x4;
    uint32_t *bh, *bl;
    int *k34, *k23, *k12;
    cudaGetSymbolAddress((void**)&cls4p, g_cls4);
    cudaGetSymbolAddress((void**)&x1, g_xyz1);
    cudaGetSymbolAddress((void**)&x2, g_xyz2);
    cudaGetSymbolAddress((void**)&x3, g_xyz3);
    cudaGetSymbolAddress((void**)&x4, g_xyz4);
    cudaGetSymbolAddress((void**)&k34, g_k34);
    cudaGetSymbolAddress((void**)&k23, g_k23);
    cudaGetSymbolAddress((void**)&k12, g_k12);
    cudaGetSymbolAddress((void**)&bh, g_Bh16);
    cudaGetSymbolAddress((void**)&bl, g_Bl16);

    cudaFuncSetAttribute(pe_mma, cudaFuncAttributeMaxDynamicSharedMemorySize, SMEMB);

    gather_kernel<<<(NL1+255)/256, 256>>>(xyz0, idx1, x1, NL1);
    gather_kernel<<<(NL2+255)/256, 256>>>(xyz0, idx2, x2, NL2);
    gather_kernel<<<(NL3+255)/256, 256>>>(xyz0, idx3, x3, NL3);
    gather_kernel<<<(NL4+255)/256, 256>>>(xyz0, idx4, x4, NL4);

    const float* Ps[5] = {P4, P3, P2, P1, P0};
    for (int i = 0; i < 5; i++)
        prep_B<<<256, 256>>>(Ps[i], bh + (size_t)i*65536, bl + (size_t)i*65536);

    cls4_kernel<<<1, 256>>>(xyz0, W_all, b_all, cls4p);

    nn_kernel<<<NL3/256, 256>>>(x3, x4, NL4, k34);
    nn_kernel<<<NL2/256, 256>>>(x2, x3, NL3, k23);
    nn_kernel<<<NL1/256, 256>>>(x1, x2, NL2, k12);

    pe_mma<<<dim3(NL4/128, 2), 256, SMEMB>>>(cls4p, k34, x4, x4, xyz0, W4, b4,
        W_all, b_all, bh + 0*(size_t)65536, bl + 0*(size_t)65536, pb4, out + OFF4, 1);
    pe_mma<<<dim3(NL3/128, 2), 256, SMEMB>>>(out + OFF4, k34, x3, x4, xyz0, W3, b3,
        W_all, b_all, bh + 1*(size_t)65536, bl + 1*(size_t)65536, pb3, out + OFF3, 0);
    pe_mma<<<dim3(NL2/128, 2), 256, SMEMB>>>(out + OFF3, k23, x2, x3, xyz0, W2, b2,
        W_all, b_all, bh + 2*(size_t)65536, bl + 2*(size_t)65536, pb2, out + OFF2, 0);
    pe_mma<<<dim3(NL1/128, 2), 256, SMEMB>>>(out + OFF2, k12, x1, x2, xyz0, W1, b1,
        W_all, b_all, bh + 3*(size_t)65536, bl + 3*(size_t)65536, pb1, out + OFF1, 0);
    pe_mma<<<dim3(NL0/128, 2), 256, SMEMB>>>(out + OFF1, idx0, xyz0, x1, xyz0, W0, b0,
        W_all, b_all, bh + 4*(size_t)65536, bl + 4*(size_t)65536, pb0, out + OFF0, 0);
}

// round 6
// speedup vs baseline: 2.3266x; 1.0119x over previous
#include <cuda_runtime.h>
#include <cuda_fp16.h>
#include <cstdint>

#define NL0 65536
#define NL1 16384
#define NL2 4096
#define NL3 1024
#define NL4 256
#define C   256
#define K2  512

#define OFF4 0
#define OFF3 (NL4*C)
#define OFF2 (OFF3 + NL3*C)
#define OFF1 (OFF2 + NL2*C)
#define OFF0 (OFF1 + NL1*C)

// B pre-split, fragment-major per level: [ch16][s2][ntg32][T32][reg2]
__device__ uint32_t g_Bh16[5][65536];
__device__ uint32_t g_Bl16[5][65536];
// f0 pre-split in smem-image layout: [rowblock512][chunk8][hi 128*20 | lo 128*20]
__device__ uint32_t g_f0F[(size_t)512 * 8 * 5120];   // 80 MB
__device__ float g_cls4[C];
__device__ float g_xyz1[NL1 * 3];
__device__ float g_xyz2[NL2 * 3];
__device__ float g_xyz3[NL3 * 3];
__device__ float g_xyz4[NL4 * 3];
__device__ int   g_k34[NL3];
__device__ int   g_k23[NL2];
__device__ int   g_k12[NL1];

__device__ __forceinline__ uint32_t smem_u32(const void* p) {
    uint32_t a;
    asm("{ .reg .u64 t; cvta.to.shared.u64 t, %1; cvt.u32.u64 %0, t; }" : "=r"(a) : "l"(p));
    return a;
}
__device__ __forceinline__ void splith(float v, __half& h, __half& l) {
    h = __float2half_rn(v);
    l = __float2half_rn(v - __half2float(h));
}
__device__ __forceinline__ uint32_t packh(__half a, __half b) {
    return (uint32_t)__half_as_ushort(a) | ((uint32_t)__half_as_ushort(b) << 16);
}
// split a pair: hi fp16x2 (v0 low), lo fp16x2 residual
__device__ __forceinline__ void split_pair(float v0, float v1, uint32_t& h, uint32_t& l) {
    __half2 hh = __float22half2_rn(make_float2(v0, v1));
    float2 bk = __half22float2(hh);
    __half2 ll = __float22half2_rn(make_float2(v0 - bk.x, v1 - bk.y));
    h = *(uint32_t*)&hh; l = *(uint32_t*)&ll;
}
__device__ __forceinline__ void mma16(float* d, const uint32_t* a, const uint32_t* b) {
    asm volatile("mma.sync.aligned.m16n8k16.row.col.f32.f16.f16.f32 "
        "{%0,%1,%2,%3}, {%4,%5,%6,%7}, {%8,%9}, {%0,%1,%2,%3};"
        : "+f"(d[0]), "+f"(d[1]), "+f"(d[2]), "+f"(d[3])
        : "r"(a[0]), "r"(a[1]), "r"(a[2]), "r"(a[3]), "r"(b[0]), "r"(b[1]));
}
#define LDM4(r, a)                                                                  \
    asm volatile("ldmatrix.sync.aligned.m8n8.x4.shared.b16 {%0,%1,%2,%3}, [%4];"    \
        : "=r"((r)[0]), "=r"((r)[1]), "=r"((r)[2]), "=r"((r)[3]) : "r"(a))

// ---------- small kernels ----------
__global__ void gather_kernel(const float* __restrict__ xyz0, const int* __restrict__ idx,
                              float* __restrict__ out, int M) {
    int i = blockIdx.x * blockDim.x + threadIdx.x;
    if (i < M) {
        int s = idx[i];
        out[i*3+0] = xyz0[s*3+0]; out[i*3+1] = xyz0[s*3+1]; out[i*3+2] = xyz0[s*3+2];
    }
}
__global__ void prep_B(const float* __restrict__ P, uint32_t* __restrict__ Bh,
                       uint32_t* __restrict__ Bl) {
    int i = blockIdx.x * 256 + threadIdx.x;
    int reg = i & 1, T = (i >> 1) & 31, ntg = (i >> 6) & 31, s = (i >> 11) & 1, ch = i >> 12;
    int k = ch*32 + s*16 + (T & 3)*2 + reg*8;
    int n = ntg*8 + (T >> 2);
    __half h0, l0, h1, l1;
    splith(P[k*C + n], h0, l0);
    splith(P[(k+1)*C + n], h1, l1);
    Bh[i] = packh(h0, h1);
    Bl[i] = packh(l0, l1);
}
// f0 split into smem-image: rows of 20 words (16 data + 4 pad), hi then lo blocks
__global__ void prep_f0(const float* __restrict__ xyz0, const float* __restrict__ W,
                        const float* __restrict__ b, uint32_t* __restrict__ f0F) {
    __shared__ float sw[1024];
    int t = threadIdx.x;
    sw[t] = W[t]; sw[256 + t] = W[256 + t]; sw[512 + t] = W[512 + t]; sw[768 + t] = b[t];
    __syncthreads();
    int rl = t >> 3, c = t & 7;
    int r = blockIdx.x * 32 + rl;
    float x = xyz0[r*3+0], y = xyz0[r*3+1], z = xyz0[r*3+2];
    uint32_t hi[16], lo[16];
    #pragma unroll
    for (int j = 0; j < 16; j++) {
        int k0 = c*32 + 2*j;
        float v0 = fmaf(x, sw[k0],   fmaf(y, sw[256+k0],   fmaf(z, sw[512+k0],   sw[768+k0])));
        float v1 = fmaf(x, sw[k0+1], fmaf(y, sw[256+k0+1], fmaf(z, sw[512+k0+1], sw[768+k0+1])));
        split_pair(v0, v1, hi[j], lo[j]);
    }
    size_t base = ((size_t)(r >> 7) * 8 + c) * 5120;
    int rw = (r & 127) * 20;
    uint4* dh = (uint4*)(f0F + base + rw);
    dh[0] = *(uint4*)&hi[0]; dh[1] = *(uint4*)&hi[4];
    dh[2] = *(uint4*)&hi[8]; dh[3] = *(uint4*)&hi[12];
    uint4* dl = (uint4*)(f0F + base + 2560 + rw);
    dl[0] = *(uint4*)&lo[0]; dl[1] = *(uint4*)&lo[4];
    dl[2] = *(uint4*)&lo[8]; dl[3] = *(uint4*)&lo[12];
}
__global__ void cls4_kernel(const float* __restrict__ xyz0, const float* __restrict__ W,
                            const float* __restrict__ b, float* __restrict__ cls4) {
    int t = threadIdx.x;
    float w0 = W[t], w1 = W[C+t], w2 = W[2*C+t], bb = b[t];
    float m = -3.4e38f;
    for (int i = 0; i < NL4; i++) {
        float v = fmaf(xyz0[i*3+0], w0, fmaf(xyz0[i*3+1], w1, fmaf(xyz0[i*3+2], w2, bb)));
        m = fmaxf(m, v);
    }
    cls4[t] = m;
}
__global__ void nn_kernel(const float* __restrict__ q, const float* __restrict__ ref, int Mr,
                          int* __restrict__ out) {
    const int CH = 1024;
    __shared__ float rx[CH], ry[CH], rz[CH], rn[CH];
    int tid = blockIdx.x * blockDim.x + threadIdx.x;
    float qx = q[tid*3+0], qy = q[tid*3+1], qz = q[tid*3+2];
    float m2x = -2.f*qx, m2y = -2.f*qy, m2z = -2.f*qz;
    float best = 3.4e38f; int bi = 0;
    for (int base = 0; base < Mr; base += CH) {
        int n = min(CH, Mr - base);
        for (int j = threadIdx.x; j < n; j += blockDim.x) {
            float x = ref[(base+j)*3+0], y = ref[(base+j)*3+1], z = ref[(base+j)*3+2];
            rx[j]=x; ry[j]=y; rz[j]=z; rn[j] = x*x + y*y + z*z;
        }
        __syncthreads();
        #pragma unroll 8
        for (int j = 0; j < n; j++) {
            float d = fmaf(m2x, rx[j], fmaf(m2y, ry[j], fmaf(m2z, rz[j], rn[j])));
            if (d < best) { best = d; bi = base + j; }
        }
        __syncthreads();
    }
    out[tid] = bi;
}

// ---------- fused level GEMM (fp16 3-pass split, ldmatrix + cp.async) ----------
// buffer words: A_hi [128 rows x 20w] | A_lo | B_hi [2][1024] | B_lo
#define AL_OFF 2560
#define B_OFF  5120
#define BUFW   9216
#define SMEMB  (2 * BUFW * 4)    // 73728 B

__global__ void __launch_bounds__(256, 2)
pe_mma(const float* __restrict__ pe_prev, const int* __restrict__ knn,
       const float* __restrict__ xyzq, const float* __restrict__ xyzr,
       const float* __restrict__ W, const float* __restrict__ b,
       const uint32_t* __restrict__ f0F,
       const uint32_t* __restrict__ Bh, const uint32_t* __restrict__ Bl,
       const float* __restrict__ pb, float* __restrict__ out, int level4)
{
    extern __shared__ uint32_t sm[];
    const int t = threadIdx.x, lane = t & 31, wid = t >> 5;
    const int wm = wid & 3, wn = wid >> 2;
    const int rowbase = blockIdx.x * 128;
    const int yb = blockIdx.y;
    const uint32_t sbase = smem_u32(sm);

    const int arow = t & 127, ah2 = t >> 7;
    const int rowg = rowbase + arow;
    float dx, dy, dz;
    const float* prow;
    {
        float qx = xyzq[rowg*3+0], qy = xyzq[rowg*3+1], qz = xyzq[rowg*3+2];
        if (level4) { prow = pe_prev; dx = qx; dy = qy; dz = qz; }
        else {
            int kk = knn[rowg];
            prow = pe_prev + (size_t)kk * C;
            dx = qx - xyzr[kk*3+0]; dy = qy - xyzr[kk*3+1]; dz = qz - xyzr[kk*3+2];
        }
    }

    #define COPY_B(c) do {                                                             \
        const int bw_ = ((c) & 1) * BUFW;                                              \
        const uint32_t* s0_ = Bh + (size_t)(c)*4096 + yb*1024 + t*4;                   \
        const uint32_t* s1_ = Bl + (size_t)(c)*4096 + yb*1024 + t*4;                   \
        _Pragma("unroll")                                                              \
        for (int s_ = 0; s_ < 2; s_++) {                                               \
            asm volatile("cp.async.cg.shared.global [%0], [%1], 16;"                   \
                :: "r"(sbase + 4*(bw_ + B_OFF + s_*1024 + t*4)),                       \
                   "l"(s0_ + s_*2048) : "memory");                                     \
            asm volatile("cp.async.cg.shared.global [%0], [%1], 16;"                   \
                :: "r"(sbase + 4*(bw_ + B_OFF + 2048 + s_*1024 + t*4)),                \
                   "l"(s1_ + s_*2048) : "memory");                                     \
        }                                                                              \
    } while (0)

    #define COPY_A(c) do {                                                             \
        const int bw_ = ((c) & 1) * BUFW;                                              \
        const uint32_t* s_ = f0F + ((size_t)(blockIdx.x*8 + (c) - 8))*5120 + t*4;      \
        _Pragma("unroll")                                                              \
        for (int i_ = 0; i_ < 5; i_++)                                                 \
            asm volatile("cp.async.cg.shared.global [%0], [%1], 16;"                   \
                :: "r"(sbase + 4*(bw_ + t*4 + i_*1024)), "l"(s_ + i_*1024) : "memory");\
    } while (0)

    #define FILL_A(c) do {                                                             \
        const int bw_ = ((c) & 1) * BUFW;                                              \
        int kg_ = (c)*32 + ah2*16;                                                     \
        float v_[16];                                                                  \
        _Pragma("unroll")                                                              \
        for (int i = 0; i < 4; i++) {                                                  \
            float4 ne = *(const float4*)(prow + kg_ + i*4);                            \
            float4 w0 = *(const float4*)(W + kg_ + i*4);                               \
            float4 w1 = *(const float4*)(W + C + kg_ + i*4);                           \
            float4 w2 = *(const float4*)(W + 2*C + kg_ + i*4);                         \
            float4 bb = *(const float4*)(b + kg_ + i*4);                               \
            v_[i*4+0] = ne.x + fmaf(dx,w0.x, fmaf(dy,w1.x, fmaf(dz,w2.x, bb.x)));      \
            v_[i*4+1] = ne.y + fmaf(dx,w0.y, fmaf(dy,w1.y, fmaf(dz,w2.y, bb.y)));      \
            v_[i*4+2] = ne.z + fmaf(dx,w0.z, fmaf(dy,w1.z, fmaf(dz,w2.z, bb.z)));      \
            v_[i*4+3] = ne.w + fmaf(dx,w0.w, fmaf(dy,w1.w, fmaf(dz,w2.w, bb.w)));      \
        }                                                                              \
        uint32_t hw_[8], lw_[8];                                                       \
        _Pragma("unroll")                                                              \
        for (int j = 0; j < 8; j++) split_pair(v_[2*j], v_[2*j+1], hw_[j], lw_[j]);    \
        uint4* dh_ = (uint4*)&sm[bw_ + arow*20 + ah2*8];                               \
        dh_[0] = *(uint4*)&hw_[0]; dh_[1] = *(uint4*)&hw_[4];                          \
        uint4* dl_ = (uint4*)&sm[bw_ + AL_OFF + arow*20 + ah2*8];                      \
        dl_[0] = *(uint4*)&lw_[0]; dl_[1] = *(uint4*)&lw_[4];                          \
    } while (0)

    float d[2][8][4];
    #pragma unroll
    for (int i = 0; i < 2; i++)
        #pragma unroll
        for (int j = 0; j < 8; j++)
            #pragma unroll
            for (int q = 0; q < 4; q++) d[i][j][q] = 0.0f;

    COPY_B(0);
    FILL_A(0);
    asm volatile("cp.async.commit_group;" ::: "memory");
    asm volatile("cp.async.wait_group 0;" ::: "memory");
    __syncthreads();

    const int r0 = lane >> 2, c0 = lane & 3;
    const int lr = (lane & 7) + ((lane >> 3) & 1) * 8;   // row within 16
    const int kseg = (lane >> 4) * 4;                    // word offset for k-halves 8-15

    for (int c = 0; c < 16; c++) {
        if (c < 15) {
            COPY_B(c + 1);
            if (c + 1 < 8) FILL_A(c + 1); else COPY_A(c + 1);
            asm volatile("cp.async.commit_group;" ::: "memory");
        }

        const int bw = (c & 1) * BUFW;
        #pragma unroll
        for (int s = 0; s < 2; s++) {
            uint32_t Afh[2][4], Afl[2][4];
            #pragma unroll
            for (int tmi = 0; tmi < 2; tmi++) {
                uint32_t aw = sbase + 4*(bw + (wm*32 + tmi*16 + lr)*20 + s*8 + kseg);
                LDM4(Afh[tmi], aw);
                LDM4(Afl[tmi], aw + AL_OFF*4);
            }
            uint32_t Bf[8][2];
            #pragma unroll
            for (int nt = 0; nt < 8; nt++) {
                int ntl = wn*8 + nt;
                *(uint2*)Bf[nt] = *(const uint2*)&sm[bw + B_OFF + s*1024 + ntl*64 + lane*2];
            }
            #pragma unroll
            for (int tmi = 0; tmi < 2; tmi++)
                #pragma unroll
                for (int nt = 0; nt < 8; nt++) mma16(d[tmi][nt], Afh[tmi], Bf[nt]);
            #pragma unroll
            for (int tmi = 0; tmi < 2; tmi++)
                #pragma unroll
                for (int nt = 0; nt < 8; nt++) mma16(d[tmi][nt], Afl[tmi], Bf[nt]);
            #pragma unroll
            for (int nt = 0; nt < 8; nt++) {
                int ntl = wn*8 + nt;
                *(uint2*)Bf[nt] = *(const uint2*)&sm[bw + B_OFF + 2048 + s*1024 + ntl*64 + lane*2];
            }
            #pragma unroll
            for (int tmi = 0; tmi < 2; tmi++)
                #pragma unroll
                for (int nt = 0; nt < 8; nt++) mma16(d[tmi][nt], Afh[tmi], Bf[nt]);
        }

        if (c < 15) asm volatile("cp.async.wait_group 0;" ::: "memory");
        __syncthreads();
    }

    #pragma unroll
    for (int tmi = 0; tmi < 2; tmi++)
        #pragma unroll
        for (int nt = 0; nt < 8; nt++) {
            int rg = rowbase + wm*32 + tmi*16 + r0;
            int cg = yb*128 + wn*64 + nt*8 + c0*2;
            float p0 = __ldg(pb + cg), p1 = __ldg(pb + cg + 1);
            *(float2*)(out + (size_t)rg*C + cg) =
                make_float2(d[tmi][nt][0] + p0, d[tmi][nt][1] + p1);
            *(float2*)(out + (size_t)(rg+8)*C + cg) =
                make_float2(d[tmi][nt][2] + p0, d[tmi][nt][3] + p1);
        }
}

// ---------- host ----------
extern "C" void kernel_launch(void* const* d_in, const int* in_sizes, int n_in,
                              void* d_out, int out_size) {
    const float* xyz0 = (const float*)d_in[0];
    const int* idx0 = (const int*)d_in[1];
    const int* idx1 = (const int*)d_in[2];
    const int* idx2 = (const int*)d_in[3];
    const int* idx3 = (const int*)d_in[4];
    const int* idx4 = (const int*)d_in[5];
    const float* W_all = (const float*)d_in[6];
    const float* b_all = (const float*)d_in[7];
    const float* W4 = (const float*)d_in[8];  const float* b4 = (const float*)d_in[9];
    const float* W3 = (const float*)d_in[10]; const float* b3 = (const float*)d_in[11];
    const float* W2 = (const float*)d_in[12]; const float* b2 = (const float*)d_in[13];
    const float* W1 = (const float*)d_in[14]; const float* b1 = (const float*)d_in[15];
    const float* W0 = (const float*)d_in[16]; const float* b0 = (const float*)d_in[17];
    const float* P4 = (const float*)d_in[18]; const float* pb4 = (const float*)d_in[19];
    const float* P3 = (const float*)d_in[20]; const float* pb3 = (const float*)d_in[21];
    const float* P2 = (const float*)d_in[22]; const float* pb2 = (const float*)d_in[23];
    const float* P1 = (const float*)d_in[24]; const float* pb1 = (const float*)d_in[25];
    const float* P0 = (const float*)d_in[26]; const float* pb0 = (const float*)d_in[27];
    float* out = (float*)d_out;

    float *cls4p, *x1, *x2, *x3, *x4;
    uint32_t *bh, *bl, *f0F;
    int *k34, *k23, *k12;
    cudaGetSymbolAddress((void**)&cls4p, g_cls4);
    cudaGetSymbolAddress((void**)&x1, g_xyz1);
    cudaGetSymbolAddress((void**)&x2, g_xyz2);
    cudaGetSymbolAddress((void**)&x3, g_xyz3);
    cudaGetSymbolAddress((void**)&x4, g_xyz4);
    cudaGetSymbolAddress((void**)&k34, g_k34);
    cudaGetSymbolAddress((void**)&k23, g_k23);
    cudaGetSymbolAddress((void**)&k12, g_k12);
    cudaGetSymbolAddress((void**)&bh, g_Bh16);
    cudaGetSymbolAddress((void**)&bl, g_Bl16);
    cudaGetSymbolAddress((void**)&f0F, g_f0F);

    cudaFuncSetAttribute(pe_mma, cudaFuncAttributeMaxDynamicSharedMemorySize, SMEMB);

    gather_kernel<<<(NL1+255)/256, 256>>>(xyz0, idx1, x1, NL1);
    gather_kernel<<<(NL2+255)/256, 256>>>(xyz0, idx2, x2, NL2);
    gather_kernel<<<(NL3+255)/256, 256>>>(xyz0, idx3, x3, NL3);
    gather_kernel<<<(NL4+255)/256, 256>>>(xyz0, idx4, x4, NL4);

    const float* Ps[5] = {P4, P3, P2, P1, P0};
    for (int i = 0; i < 5; i++)
        prep_B<<<256, 256>>>(Ps[i], bh + (size_t)i*65536, bl + (size_t)i*65536);

    prep_f0<<<NL0/32, 256>>>(xyz0, W_all, b_all, f0F);
    cls4_kernel<<<1, 256>>>(xyz0, W_all, b_all, cls4p);

    nn_kernel<<<NL3/256, 256>>>(x3, x4, NL4, k34);
    nn_kernel<<<NL2/256, 256>>>(x2, x3, NL3, k23);
    nn_kernel<<<NL1/256, 256>>>(x1, x2, NL2, k12);

    pe_mma<<<dim3(NL4/128, 2), 256, SMEMB>>>(cls4p, k34, x4, x4, W4, b4, f0F,
        bh + 0*(size_t)65536, bl + 0*(size_t)65536, pb4, out + OFF4, 1);
    pe_mma<<<dim3(NL3/128, 2), 256, SMEMB>>>(out + OFF4, k34, x3, x4, W3, b3, f0F,
        bh + 1*(size_t)65536, bl + 1*(size_t)65536, pb3, out + OFF3, 0);
    pe_mma<<<dim3(NL2/128, 2), 256, SMEMB>>>(out + OFF3, k23, x2, x3, W2, b2, f0F,
        bh + 2*(size_t)65536, bl + 2*(size_t)65536, pb2, out + OFF2, 0);
    pe_mma<<<dim3(NL1/128, 2), 256, SMEMB>>>(out + OFF2, k12, x1, x2, W1, b1, f0F,
        bh + 3*(size_t)65536, bl + 3*(size_t)65536, pb1, out + OFF1, 0);
    pe_mma<<<dim3(NL0/128, 2), 256, SMEMB>>>(out + OFF1, idx0, xyz0, x1, W0, b0, f0F,
        bh + 4*(size_t)65536, bl + 4*(size_t)65536, pb0, out + OFF0, 0);
}